// round 2
// baseline (speedup 1.0000x reference)
#include <cuda_runtime.h>

// ---------------- problem constants ----------------
#define BB    8
#define CIN   80
#define LL    4096
#define DM    256
#define NB    4
#define DI    512      // d_inner
#define DS    2        // d_state
#define DC    7
#define DTR   16
#define ROWS  (BB*LL)  // 32768

#define NC    32       // scan chunks per sequence
#define CHUNK (LL/NC)  // 128

// ---------------- scratch (device globals; no allocations) ----------------
__device__ float g_h[ROWS*DM];          // hidden between blocks   (33.5 MB)
__device__ float g_xz[ROWS*2*DI];       // in_proj output          (134 MB)
__device__ float g_xi[ROWS*DI];         // silu(conv(x))           (67 MB)
__device__ float g_delta[ROWS*DI];      // softplus delta          (67 MB)
__device__ float g_bc[ROWS*4];          // B0,B1,C0,C1 per row
__device__ float g_y[ROWS*DI];          // gated output pre-out_w  (67 MB)
__device__ float g_P[BB*DI*NC*2];       // chunk decay products
__device__ float g_Hp[BB*DI*NC*2];      // chunk partial states
__device__ float g_hinit[BB*DI*NC*2];   // corrected chunk initial states
__device__ float g_partial[BB*32*DM];   // mean partials

__device__ __forceinline__ float siluf(float x) { return x / (1.f + __expf(-x)); }
__device__ __forceinline__ float softplusf(float x) {
    if (x > 20.f) return x;
    return log1pf(__expf(x));
}

// ---------------- input projection: h[b,l,c] = sum_k x[b,k,l]*pw[c,k] + pb[c] ----------------
__global__ __launch_bounds__(256) void proj_kernel(const float* __restrict__ x,
                                                   const float* __restrict__ pw,
                                                   const float* __restrict__ pb) {
    __shared__ float xs[16][CIN];
    const int r0  = blockIdx.x * 16;
    const int tid = threadIdx.x;
    for (int i = tid; i < 16 * CIN; i += 256) {
        int rr = i / CIN, k = i % CIN;
        int row = r0 + rr;
        int b = row / LL, l = row % LL;
        xs[rr][k] = x[(b * CIN + k) * LL + l];
    }
    __syncthreads();
    const int c = tid;                 // 256 threads = 256 output channels
    float acc[16];
    float bias = pb[c];
#pragma unroll
    for (int r = 0; r < 16; r++) acc[r] = bias;
    for (int k = 0; k < CIN; k++) {
        float w = pw[c * CIN + k];
#pragma unroll
        for (int r = 0; r < 16; r++) acc[r] += w * xs[r][k];
    }
#pragma unroll
    for (int r = 0; r < 16; r++) g_h[(r0 + r) * DM + c] = acc[r];
}

// ---------------- SGEMM: C[m,n] = sum_k A[m*K+k]*W[n*K+k]  (M%128==0, N%128==0, K%8==0) ----------------
__global__ __launch_bounds__(256) void sgemm_nt(const float* __restrict__ A,
                                                const float* __restrict__ W,
                                                float* __restrict__ C,
                                                int M, int N, int K) {
    __shared__ float As[8][132];
    __shared__ float Ws[8][132];
    const int tid = threadIdx.x;
    const int tx  = tid & 15;          // 16 in N
    const int ty  = tid >> 4;          // 16 in M
    const int m0  = blockIdx.y * 128;
    const int n0  = blockIdx.x * 128;
    const int lr  = tid >> 1;          // 0..127
    const int lk  = (tid & 1) * 4;     // 0 or 4
    const float* Aptr = A + (size_t)(m0 + lr) * K + lk;
    const float* Wptr = W + (size_t)(n0 + lr) * K + lk;

    float acc[8][8];
#pragma unroll
    for (int i = 0; i < 8; i++)
#pragma unroll
        for (int j = 0; j < 8; j++) acc[i][j] = 0.f;

    for (int k0 = 0; k0 < K; k0 += 8) {
        float4 av = *reinterpret_cast<const float4*>(Aptr + k0);
        float4 wv = *reinterpret_cast<const float4*>(Wptr + k0);
        __syncthreads();
        As[lk + 0][lr] = av.x; As[lk + 1][lr] = av.y; As[lk + 2][lr] = av.z; As[lk + 3][lr] = av.w;
        Ws[lk + 0][lr] = wv.x; Ws[lk + 1][lr] = wv.y; Ws[lk + 2][lr] = wv.z; Ws[lk + 3][lr] = wv.w;
        __syncthreads();
#pragma unroll
        for (int k = 0; k < 8; k++) {
            float a[8], w[8];
            *(float4*)&a[0] = *(const float4*)&As[k][ty * 4];
            *(float4*)&a[4] = *(const float4*)&As[k][64 + ty * 4];
            *(float4*)&w[0] = *(const float4*)&Ws[k][tx * 4];
            *(float4*)&w[4] = *(const float4*)&Ws[k][64 + tx * 4];
#pragma unroll
            for (int i = 0; i < 8; i++)
#pragma unroll
                for (int j = 0; j < 8; j++) acc[i][j] += a[i] * w[j];
        }
    }
#pragma unroll
    for (int ih = 0; ih < 2; ih++) {
#pragma unroll
        for (int ii = 0; ii < 4; ii++) {
            int m = m0 + ih * 64 + ty * 4 + ii;
            float* Crow = C + (size_t)m * N + n0;
            int i = ih * 4 + ii;
            *(float4*)&Crow[tx * 4]      = make_float4(acc[i][0], acc[i][1], acc[i][2], acc[i][3]);
            *(float4*)&Crow[64 + tx * 4] = make_float4(acc[i][4], acc[i][5], acc[i][6], acc[i][7]);
        }
    }
}

// ---------------- causal depthwise conv7 + bias + silu ----------------
__global__ __launch_bounds__(256) void conv_silu_kernel(const float* __restrict__ cw,
                                                        const float* __restrict__ cb) {
    int idx = blockIdx.x * blockDim.x + threadIdx.x;   // over ROWS*DI
    int d   = idx % DI;
    int row = idx / DI;
    int l   = row % LL;
    float w[7];
#pragma unroll
    for (int j = 0; j < 7; j++) w[j] = cw[d * 7 + j];
    float acc = cb[d];
#pragma unroll
    for (int j = 0; j < 7; j++) {
        int ls = l - 6 + j;
        if (ls >= 0) acc += w[j] * g_xz[(size_t)(row - 6 + j) * (2 * DI) + d];
    }
    g_xi[idx] = siluf(acc);
}

// ---------------- per-row: x_dbl = xi @ xproj_wT ; delta = softplus(x_dbl[:16]@dt_wT + dt_b) ----------------
__global__ __launch_bounds__(128) void xdbl_delta_kernel(const float* __restrict__ xpw,
                                                         const float* __restrict__ dtw,
                                                         const float* __restrict__ dtb) {
    __shared__ float xs[DI];
    __shared__ float xd[20];
    const int row = blockIdx.x;
    const int tid = threadIdx.x;
    const float* xr = g_xi + (size_t)row * DI;
#pragma unroll
    for (int i = 0; i < 4; i++) xs[tid + i * 128] = xr[tid + i * 128];
    __syncthreads();
    const int warp = tid >> 5, lane = tid & 31;
    for (int j = warp; j < 20; j += 4) {
        const float* wj = xpw + j * DI;
        float s = 0.f;
        for (int k = lane; k < DI; k += 32) s += xs[k] * wj[k];
#pragma unroll
        for (int off = 16; off; off >>= 1) s += __shfl_xor_sync(0xffffffff, s, off);
        if (lane == 0) xd[j] = s;
    }
    __syncthreads();
#pragma unroll
    for (int i = 0; i < 4; i++) {
        int d = tid + i * 128;
        float s = dtb[d];
        const float4* wr = (const float4*)(dtw + d * DTR);
#pragma unroll
        for (int q = 0; q < 4; q++) {
            float4 v = wr[q];
            s += v.x * xd[q * 4 + 0] + v.y * xd[q * 4 + 1] + v.z * xd[q * 4 + 2] + v.w * xd[q * 4 + 3];
        }
        g_delta[(size_t)row * DI + d] = softplusf(s);
    }
    if (tid < 4) g_bc[row * 4 + tid] = xd[16 + tid];
}

// ---------------- scan phase 1: per (b,d,chunk) partial scan from zero state ----------------
__global__ __launch_bounds__(256) void scan1_kernel(const float* __restrict__ Alog) {
    int idx = blockIdx.x * blockDim.x + threadIdx.x;   // B*NC*DI
    int d = idx % DI;
    int c = (idx / DI) % NC;
    int b = idx / (DI * NC);
    float A0 = -__expf(Alog[d * 2 + 0]);
    float A1 = -__expf(Alog[d * 2 + 1]);
    float h0 = 0.f, h1 = 0.f, P0 = 1.f, P1 = 1.f;
    int rowbase = b * LL + c * CHUNK;
    for (int t = 0; t < CHUNK; t++) {
        int row = rowbase + t;
        float dl = g_delta[(size_t)row * DI + d];
        float u  = g_xi[(size_t)row * DI + d];
        float B0 = g_bc[row * 4 + 0];
        float B1 = g_bc[row * 4 + 1];
        float dA0 = __expf(dl * A0);
        float dA1 = __expf(dl * A1);
        float du  = dl * u;
        h0 = dA0 * h0 + du * B0;
        h1 = dA1 * h1 + du * B1;
        P0 *= dA0; P1 *= dA1;
    }
    int o = ((b * DI + d) * NC + c) * 2;
    g_P[o] = P0;  g_P[o + 1] = P1;
    g_Hp[o] = h0; g_Hp[o + 1] = h1;
}

// ---------------- scan phase 2: combine chunk states sequentially (32 steps) ----------------
__global__ __launch_bounds__(256) void scan2_kernel() {
    int idx = blockIdx.x * blockDim.x + threadIdx.x;   // B*DI
    if (idx >= BB * DI) return;
    int base = idx * NC;
    float h0 = 0.f, h1 = 0.f;
    for (int c = 0; c < NC; c++) {
        int o = (base + c) * 2;
        g_hinit[o] = h0; g_hinit[o + 1] = h1;
        h0 = g_P[o] * h0 + g_Hp[o];
        h1 = g_P[o + 1] * h1 + g_Hp[o + 1];
    }
}

// ---------------- scan phase 3: replay with correct init; fuse y = (h.C + xi*D) * silu(res) ----------------
__global__ __launch_bounds__(256) void scan3_kernel(const float* __restrict__ Alog,
                                                    const float* __restrict__ Dp) {
    int idx = blockIdx.x * blockDim.x + threadIdx.x;   // B*NC*DI
    int d = idx % DI;
    int c = (idx / DI) % NC;
    int b = idx / (DI * NC);
    float A0 = -__expf(Alog[d * 2 + 0]);
    float A1 = -__expf(Alog[d * 2 + 1]);
    int o = ((b * DI + d) * NC + c) * 2;
    float h0 = g_hinit[o], h1 = g_hinit[o + 1];
    float Dd = Dp[d];
    int rowbase = b * LL + c * CHUNK;
    for (int t = 0; t < CHUNK; t++) {
        int row = rowbase + t;
        float dl = g_delta[(size_t)row * DI + d];
        float u  = g_xi[(size_t)row * DI + d];
        float B0 = g_bc[row * 4 + 0];
        float B1 = g_bc[row * 4 + 1];
        float C0 = g_bc[row * 4 + 2];
        float C1 = g_bc[row * 4 + 3];
        float dA0 = __expf(dl * A0);
        float dA1 = __expf(dl * A1);
        float du  = dl * u;
        h0 = dA0 * h0 + du * B0;
        h1 = dA1 * h1 + du * B1;
        float y = h0 * C0 + h1 * C1 + u * Dd;
        float r = g_xz[(size_t)row * (2 * DI) + DI + d];
        g_y[(size_t)row * DI + d] = y * siluf(r);
    }
}

// ---------------- mean over sequence ----------------
__global__ __launch_bounds__(256) void mean1_kernel() {
    int blk = blockIdx.x;          // BB*32
    int b = blk / 32;
    int lc = blk % 32;
    int c = threadIdx.x;           // 256
    float s = 0.f;
    int l0 = lc * 128;
    for (int l = l0; l < l0 + 128; l++) s += g_h[(size_t)(b * LL + l) * DM + c];
    g_partial[(b * 32 + lc) * DM + c] = s;
}
__global__ __launch_bounds__(256) void mean2_kernel(float* __restrict__ out) {
    int idx = blockIdx.x * blockDim.x + threadIdx.x;   // BB*DM
    if (idx >= BB * DM) return;
    int b = idx / DM, c = idx % DM;
    float s = 0.f;
    for (int lc = 0; lc < 32; lc++) s += g_partial[(b * 32 + lc) * DM + c];
    out[idx] = s * (1.f / LL);
}

// ---------------- launcher ----------------
extern "C" void kernel_launch(void* const* d_in, const int* in_sizes, int n_in,
                              void* d_out, int out_size) {
    (void)in_sizes; (void)n_in; (void)out_size;
    const float* x       = (const float*)d_in[0];
    const float* proj_w  = (const float*)d_in[1];
    const float* proj_b  = (const float*)d_in[2];
    const float* in_w    = (const float*)d_in[3];
    const float* conv_w  = (const float*)d_in[4];
    const float* conv_b  = (const float*)d_in[5];
    const float* xproj_w = (const float*)d_in[6];
    const float* dt_w    = (const float*)d_in[7];
    const float* dt_b    = (const float*)d_in[8];
    const float* A_log   = (const float*)d_in[9];
    const float* Dp      = (const float*)d_in[10];
    const float* out_w   = (const float*)d_in[11];

    float *p_h, *p_xz, *p_y;
    cudaGetSymbolAddress((void**)&p_h,  g_h);
    cudaGetSymbolAddress((void**)&p_xz, g_xz);
    cudaGetSymbolAddress((void**)&p_y,  g_y);

    proj_kernel<<<ROWS / 16, 256>>>(x, proj_w, proj_b);

    for (int i = 0; i < NB; i++) {
        const float* in_w_i    = in_w    + (size_t)i * 2 * DI * DM;
        const float* conv_w_i  = conv_w  + (size_t)i * DI * DC;
        const float* conv_b_i  = conv_b  + (size_t)i * DI;
        const float* xproj_w_i = xproj_w + (size_t)i * (DTR + 2 * DS) * DI;
        const float* dt_w_i    = dt_w    + (size_t)i * DI * DTR;
        const float* dt_b_i    = dt_b    + (size_t)i * DI;
        const float* A_log_i   = A_log   + (size_t)i * DI * DS;
        const float* Dp_i      = Dp      + (size_t)i * DI;
        const float* out_w_i   = out_w   + (size_t)i * DM * DI;

        // xz = h @ in_w^T : (32768x256)x(1024x256)^T
        sgemm_nt<<<dim3(2 * DI / 128, ROWS / 128), 256>>>(p_h, in_w_i, p_xz, ROWS, 2 * DI, DM);
        // xi = silu(conv(xz[:, :DI]) + b)
        conv_silu_kernel<<<(ROWS * DI) / 256, 256>>>(conv_w_i, conv_b_i);
        // x_dbl + delta + B/C
        xdbl_delta_kernel<<<ROWS, 128>>>(xproj_w_i, dt_w_i, dt_b_i);
        // chunked selective scan
        scan1_kernel<<<(BB * NC * DI) / 256, 256>>>(A_log_i);
        scan2_kernel<<<(BB * DI + 255) / 256, 256>>>();
        scan3_kernel<<<(BB * NC * DI) / 256, 256>>>(A_log_i, Dp_i);
        // h = y @ out_w^T : (32768x512)x(256x512)^T
        sgemm_nt<<<dim3(DM / 128, ROWS / 128), 256>>>(p_y, out_w_i, p_h, ROWS, DM, DI);
    }

    mean1_kernel<<<BB * 32, 256>>>();
    mean2_kernel<<<(BB * DM + 255) / 256, 256>>>((float*)d_out);
}

// round 3
// speedup vs baseline: 1.0013x; 1.0013x over previous
#include <cuda_runtime.h>

// ---------------- problem constants ----------------
#define BB    8
#define CIN   80
#define LL    4096
#define DM    256
#define NB    4
#define DI    512      // d_inner
#define DS    2        // d_state
#define DC    7
#define DTR   16
#define ROWS  (BB*LL)  // 32768

#define NC    32       // scan chunks per sequence
#define CHUNK (LL/NC)  // 128

// ---------------- scratch (device globals; no allocations) ----------------
__device__ float g_h[ROWS*DM];          // hidden between blocks   (33.5 MB)
__device__ float g_xz[ROWS*2*DI];       // in_proj output          (134 MB)
__device__ float g_xi[ROWS*DI];         // silu(conv(x))           (67 MB)
__device__ float g_delta[ROWS*DI];      // softplus delta          (67 MB)
__device__ float g_bc[ROWS*4];          // B0,B1,C0,C1 per row
__device__ float g_y[ROWS*DI];          // gated output pre-out_w  (67 MB)
__device__ float g_P[BB*DI*NC*2];       // chunk decay products
__device__ float g_Hp[BB*DI*NC*2];      // chunk partial states
__device__ float g_hinit[BB*DI*NC*2];   // corrected chunk initial states
__device__ float g_partial[BB*32*DM];   // mean partials

__device__ __forceinline__ float siluf(float x) { return x / (1.f + __expf(-x)); }
__device__ __forceinline__ float softplusf(float x) {
    if (x > 20.f) return x;
    return log1pf(__expf(x));
}

// ---------------- input projection: h[b,l,c] = sum_k x[b,k,l]*pw[c,k] + pb[c] ----------------
__global__ __launch_bounds__(256) void proj_kernel(const float* __restrict__ x,
                                                   const float* __restrict__ pw,
                                                   const float* __restrict__ pb) {
    __shared__ float xs[16][CIN];
    const int r0  = blockIdx.x * 16;
    const int tid = threadIdx.x;
    for (int i = tid; i < 16 * CIN; i += 256) {
        int rr = i / CIN, k = i % CIN;
        int row = r0 + rr;
        int b = row / LL, l = row % LL;
        xs[rr][k] = x[(b * CIN + k) * LL + l];
    }
    __syncthreads();
    const int c = tid;                 // 256 threads = 256 output channels
    float acc[16];
    float bias = pb[c];
#pragma unroll
    for (int r = 0; r < 16; r++) acc[r] = bias;
    for (int k = 0; k < CIN; k++) {
        float w = pw[c * CIN + k];
#pragma unroll
        for (int r = 0; r < 16; r++) acc[r] += w * xs[r][k];
    }
#pragma unroll
    for (int r = 0; r < 16; r++) g_h[(r0 + r) * DM + c] = acc[r];
}

// ---------------- SGEMM: C[m,n] = sum_k A[m*K+k]*W[n*K+k]  (M%128==0, N%128==0, K%8==0) ----------------
__global__ __launch_bounds__(256) void sgemm_nt(const float* __restrict__ A,
                                                const float* __restrict__ W,
                                                float* __restrict__ C,
                                                int M, int N, int K) {
    __shared__ float As[8][132];
    __shared__ float Ws[8][132];
    const int tid = threadIdx.x;
    const int tx  = tid & 15;          // 16 in N
    const int ty  = tid >> 4;          // 16 in M
    const int m0  = blockIdx.y * 128;
    const int n0  = blockIdx.x * 128;
    const int lr  = tid >> 1;          // 0..127
    const int lk  = (tid & 1) * 4;     // 0 or 4
    const float* Aptr = A + (size_t)(m0 + lr) * K + lk;
    const float* Wptr = W + (size_t)(n0 + lr) * K + lk;

    float acc[8][8];
#pragma unroll
    for (int i = 0; i < 8; i++)
#pragma unroll
        for (int j = 0; j < 8; j++) acc[i][j] = 0.f;

    for (int k0 = 0; k0 < K; k0 += 8) {
        float4 av = *reinterpret_cast<const float4*>(Aptr + k0);
        float4 wv = *reinterpret_cast<const float4*>(Wptr + k0);
        __syncthreads();
        As[lk + 0][lr] = av.x; As[lk + 1][lr] = av.y; As[lk + 2][lr] = av.z; As[lk + 3][lr] = av.w;
        Ws[lk + 0][lr] = wv.x; Ws[lk + 1][lr] = wv.y; Ws[lk + 2][lr] = wv.z; Ws[lk + 3][lr] = wv.w;
        __syncthreads();
#pragma unroll
        for (int k = 0; k < 8; k++) {
            float a[8], w[8];
            *(float4*)&a[0] = *(const float4*)&As[k][ty * 4];
            *(float4*)&a[4] = *(const float4*)&As[k][64 + ty * 4];
            *(float4*)&w[0] = *(const float4*)&Ws[k][tx * 4];
            *(float4*)&w[4] = *(const float4*)&Ws[k][64 + tx * 4];
#pragma unroll
            for (int i = 0; i < 8; i++)
#pragma unroll
                for (int j = 0; j < 8; j++) acc[i][j] += a[i] * w[j];
        }
    }
#pragma unroll
    for (int ih = 0; ih < 2; ih++) {
#pragma unroll
        for (int ii = 0; ii < 4; ii++) {
            int m = m0 + ih * 64 + ty * 4 + ii;
            float* Crow = C + (size_t)m * N + n0;
            int i = ih * 4 + ii;
            *(float4*)&Crow[tx * 4]      = make_float4(acc[i][0], acc[i][1], acc[i][2], acc[i][3]);
            *(float4*)&Crow[64 + tx * 4] = make_float4(acc[i][4], acc[i][5], acc[i][6], acc[i][7]);
        }
    }
}

// ---------------- causal depthwise conv7 + bias + silu ----------------
__global__ __launch_bounds__(256) void conv_silu_kernel(const float* __restrict__ cw,
                                                        const float* __restrict__ cb) {
    int idx = blockIdx.x * blockDim.x + threadIdx.x;   // over ROWS*DI
    int d   = idx % DI;
    int row = idx / DI;
    int l   = row % LL;
    float w[7];
#pragma unroll
    for (int j = 0; j < 7; j++) w[j] = cw[d * 7 + j];
    float acc = cb[d];
#pragma unroll
    for (int j = 0; j < 7; j++) {
        int ls = l - 6 + j;
        if (ls >= 0) acc += w[j] * g_xz[(size_t)(row - 6 + j) * (2 * DI) + d];
    }
    g_xi[idx] = siluf(acc);
}

// ---------------- per-row: x_dbl = xi @ xproj_wT ; delta = softplus(x_dbl[:16]@dt_wT + dt_b) ----------------
__global__ __launch_bounds__(128) void xdbl_delta_kernel(const float* __restrict__ xpw,
                                                         const float* __restrict__ dtw,
                                                         const float* __restrict__ dtb) {
    __shared__ float xs[DI];
    __shared__ float xd[20];
    const int row = blockIdx.x;
    const int tid = threadIdx.x;
    const float* xr = g_xi + (size_t)row * DI;
#pragma unroll
    for (int i = 0; i < 4; i++) xs[tid + i * 128] = xr[tid + i * 128];
    __syncthreads();
    const int warp = tid >> 5, lane = tid & 31;
    for (int j = warp; j < 20; j += 4) {
        const float* wj = xpw + j * DI;
        float s = 0.f;
        for (int k = lane; k < DI; k += 32) s += xs[k] * wj[k];
#pragma unroll
        for (int off = 16; off; off >>= 1) s += __shfl_xor_sync(0xffffffff, s, off);
        if (lane == 0) xd[j] = s;
    }
    __syncthreads();
#pragma unroll
    for (int i = 0; i < 4; i++) {
        int d = tid + i * 128;
        float s = dtb[d];
        const float4* wr = (const float4*)(dtw + d * DTR);
#pragma unroll
        for (int q = 0; q < 4; q++) {
            float4 v = wr[q];
            s += v.x * xd[q * 4 + 0] + v.y * xd[q * 4 + 1] + v.z * xd[q * 4 + 2] + v.w * xd[q * 4 + 3];
        }
        g_delta[(size_t)row * DI + d] = softplusf(s);
    }
    if (tid < 4) g_bc[row * 4 + tid] = xd[16 + tid];
}

// ---------------- scan phase 1: per (b,d,chunk) partial scan from zero state ----------------
__global__ __launch_bounds__(256) void scan1_kernel(const float* __restrict__ Alog) {
    int idx = blockIdx.x * blockDim.x + threadIdx.x;   // B*NC*DI
    int d = idx % DI;
    int c = (idx / DI) % NC;
    int b = idx / (DI * NC);
    float A0 = -__expf(Alog[d * 2 + 0]);
    float A1 = -__expf(Alog[d * 2 + 1]);
    float h0 = 0.f, h1 = 0.f, P0 = 1.f, P1 = 1.f;
    int rowbase = b * LL + c * CHUNK;
    for (int t = 0; t < CHUNK; t++) {
        int row = rowbase + t;
        float dl = g_delta[(size_t)row * DI + d];
        float u  = g_xi[(size_t)row * DI + d];
        float B0 = g_bc[row * 4 + 0];
        float B1 = g_bc[row * 4 + 1];
        float dA0 = __expf(dl * A0);
        float dA1 = __expf(dl * A1);
        float du  = dl * u;
        h0 = dA0 * h0 + du * B0;
        h1 = dA1 * h1 + du * B1;
        P0 *= dA0; P1 *= dA1;
    }
    int o = ((b * DI + d) * NC + c) * 2;
    g_P[o] = P0;  g_P[o + 1] = P1;
    g_Hp[o] = h0; g_Hp[o + 1] = h1;
}

// ---------------- scan phase 2: combine chunk states sequentially (32 steps) ----------------
__global__ __launch_bounds__(256) void scan2_kernel() {
    int idx = blockIdx.x * blockDim.x + threadIdx.x;   // B*DI
    if (idx >= BB * DI) return;
    int base = idx * NC;
    float h0 = 0.f, h1 = 0.f;
    for (int c = 0; c < NC; c++) {
        int o = (base + c) * 2;
        g_hinit[o] = h0; g_hinit[o + 1] = h1;
        h0 = g_P[o] * h0 + g_Hp[o];
        h1 = g_P[o + 1] * h1 + g_Hp[o + 1];
    }
}

// ---------------- scan phase 3: replay with correct init; fuse y = (h.C + xi*D) * silu(res) ----------------
__global__ __launch_bounds__(256) void scan3_kernel(const float* __restrict__ Alog,
                                                    const float* __restrict__ Dp) {
    int idx = blockIdx.x * blockDim.x + threadIdx.x;   // B*NC*DI
    int d = idx % DI;
    int c = (idx / DI) % NC;
    int b = idx / (DI * NC);
    float A0 = -__expf(Alog[d * 2 + 0]);
    float A1 = -__expf(Alog[d * 2 + 1]);
    int o = ((b * DI + d) * NC + c) * 2;
    float h0 = g_hinit[o], h1 = g_hinit[o + 1];
    float Dd = Dp[d];
    int rowbase = b * LL + c * CHUNK;
    for (int t = 0; t < CHUNK; t++) {
        int row = rowbase + t;
        float dl = g_delta[(size_t)row * DI + d];
        float u  = g_xi[(size_t)row * DI + d];
        float B0 = g_bc[row * 4 + 0];
        float B1 = g_bc[row * 4 + 1];
        float C0 = g_bc[row * 4 + 2];
        float C1 = g_bc[row * 4 + 3];
        float dA0 = __expf(dl * A0);
        float dA1 = __expf(dl * A1);
        float du  = dl * u;
        h0 = dA0 * h0 + du * B0;
        h1 = dA1 * h1 + du * B1;
        float y = h0 * C0 + h1 * C1 + u * Dd;
        float r = g_xz[(size_t)row * (2 * DI) + DI + d];
        g_y[(size_t)row * DI + d] = y * siluf(r);
    }
}

// ---------------- mean over sequence ----------------
__global__ __launch_bounds__(256) void mean1_kernel() {
    int blk = blockIdx.x;          // BB*32
    int b = blk / 32;
    int lc = blk % 32;
    int c = threadIdx.x;           // 256
    float s = 0.f;
    int l0 = lc * 128;
    for (int l = l0; l < l0 + 128; l++) s += g_h[(size_t)(b * LL + l) * DM + c];
    g_partial[(b * 32 + lc) * DM + c] = s;
}
__global__ __launch_bounds__(256) void mean2_kernel(float* __restrict__ out) {
    int idx = blockIdx.x * blockDim.x + threadIdx.x;   // BB*DM
    if (idx >= BB * DM) return;
    int b = idx / DM, c = idx % DM;
    float s = 0.f;
    for (int lc = 0; lc < 32; lc++) s += g_partial[(b * 32 + lc) * DM + c];
    out[idx] = s * (1.f / LL);
}

// ---------------- launcher ----------------
extern "C" void kernel_launch(void* const* d_in, const int* in_sizes, int n_in,
                              void* d_out, int out_size) {
    (void)in_sizes; (void)n_in; (void)out_size;
    const float* x       = (const float*)d_in[0];
    const float* proj_w  = (const float*)d_in[1];
    const float* proj_b  = (const float*)d_in[2];
    const float* in_w    = (const float*)d_in[3];
    const float* conv_w  = (const float*)d_in[4];
    const float* conv_b  = (const float*)d_in[5];
    const float* xproj_w = (const float*)d_in[6];
    const float* dt_w    = (const float*)d_in[7];
    const float* dt_b    = (const float*)d_in[8];
    const float* A_log   = (const float*)d_in[9];
    const float* Dp      = (const float*)d_in[10];
    const float* out_w   = (const float*)d_in[11];

    float *p_h, *p_xz, *p_y;
    cudaGetSymbolAddress((void**)&p_h,  g_h);
    cudaGetSymbolAddress((void**)&p_xz, g_xz);
    cudaGetSymbolAddress((void**)&p_y,  g_y);

    proj_kernel<<<ROWS / 16, 256>>>(x, proj_w, proj_b);

    for (int i = 0; i < NB; i++) {
        const float* in_w_i    = in_w    + (size_t)i * 2 * DI * DM;
        const float* conv_w_i  = conv_w  + (size_t)i * DI * DC;
        const float* conv_b_i  = conv_b  + (size_t)i * DI;
        const float* xproj_w_i = xproj_w + (size_t)i * (DTR + 2 * DS) * DI;
        const float* dt_w_i    = dt_w    + (size_t)i * DI * DTR;
        const float* dt_b_i    = dt_b    + (size_t)i * DI;
        const float* A_log_i   = A_log   + (size_t)i * DI * DS;
        const float* Dp_i      = Dp      + (size_t)i * DI;
        const float* out_w_i   = out_w   + (size_t)i * DM * DI;

        // xz = h @ in_w^T : (32768x256)x(1024x256)^T
        sgemm_nt<<<dim3(2 * DI / 128, ROWS / 128), 256>>>(p_h, in_w_i, p_xz, ROWS, 2 * DI, DM);
        // xi = silu(conv(xz[:, :DI]) + b)
        conv_silu_kernel<<<(ROWS * DI) / 256, 256>>>(conv_w_i, conv_b_i);
        // x_dbl + delta + B/C
        xdbl_delta_kernel<<<ROWS, 128>>>(xproj_w_i, dt_w_i, dt_b_i);
        // chunked selective scan
        scan1_kernel<<<(BB * NC * DI) / 256, 256>>>(A_log_i);
        scan2_kernel<<<(BB * DI + 255) / 256, 256>>>();
        scan3_kernel<<<(BB * NC * DI) / 256, 256>>>(A_log_i, Dp_i);
        // h = y @ out_w^T : (32768x512)x(256x512)^T
        sgemm_nt<<<dim3(DM / 128, ROWS / 128), 256>>>(p_y, out_w_i, p_h, ROWS, DM, DI);
    }

    mean1_kernel<<<BB * 32, 256>>>();
    mean2_kernel<<<(BB * DM + 255) / 256, 256>>>((float*)d_out);
}